// round 1
// baseline (speedup 1.0000x reference)
#include <cuda_runtime.h>
#include <cstdint>

// Fixed problem geometry: H=W=2048, step=2 -> nu=nv=1024, N=2^20 nodes.
constexpr int NU = 1024;
constexpr int NV = 1024;
constexpr int N  = NU * NV;        // 1048576
constexpr int W  = 2048;

// Output layout (concatenated tuple): pts[3N] nrm[3N] radii[N] lens[4N] areas[2N]
constexpr long long OFF_PTS  = 0;
constexpr long long OFF_NRM  = 3LL * N;
constexpr long long OFF_RAD  = 6LL * N;
constexpr long long OFF_LEN  = 7LL * N;
constexpr long long OFF_AREA = 11LL * N;

struct F3 { float x, y, z; };

__device__ __forceinline__ F3 load3_aligned8(const float* __restrict__ p) {
    // p is 8-byte aligned (byte offset is a multiple of 24)
    float2 ab = *reinterpret_cast<const float2*>(p);
    F3 r; r.x = ab.x; r.y = ab.y; r.z = p[2];
    return r;
}

__device__ __forceinline__ F3 load3(const float* __restrict__ p) {
    F3 r; r.x = p[0]; r.y = p[1]; r.z = p[2];
    return r;
}

__device__ __forceinline__ float dist3(const F3& a, const F3& b) {
    float dx = a.x - b.x, dy = a.y - b.y, dz = a.z - b.z;
    return sqrtf(dx * dx + dy * dy + dz * dz);
}

// ---------------------------------------------------------------------------
// Kernel 1: gather anchor points + normals into out (pts, nrm sections).
// One thread per node. pix = (2*jv)*W + 2*iu ; reads 12B @ stride 24B.
// ---------------------------------------------------------------------------
__global__ __launch_bounds__(256)
void k_gather(const float* __restrict__ cand,
              const float* __restrict__ cnrm,
              float* __restrict__ out) {
    int k = blockIdx.x * blockDim.x + threadIdx.x;
    if (k >= N) return;
    int iu = k & (NU - 1);
    int jv = k >> 10;
    long long pix = (long long)(2 * jv) * W + 2 * iu;   // even -> pix*12 is 8-aligned
    F3 c = load3_aligned8(cand + pix * 3);
    F3 n = load3_aligned8(cnrm + pix * 3);
    float* po = out + OFF_PTS + 3LL * k;
    po[0] = c.x; po[1] = c.y; po[2] = c.z;
    float* no = out + OFF_NRM + 3LL * k;
    no[0] = n.x; no[1] = n.y; no[2] = n.z;
}

// ---------------------------------------------------------------------------
// Kernel 2: per-node 4 edge lengths + 2 triangle areas, reading dense pts.
// Edge order matches reference concat: [right, diag, down, anti-diag].
// ---------------------------------------------------------------------------
__global__ __launch_bounds__(256)
void k_edges(const float* __restrict__ pts, float* __restrict__ out) {
    int k = blockIdx.x * blockDim.x + threadIdx.x;
    if (k >= N) return;
    int iu = k & (NU - 1);
    int jv = k >> 10;
    bool re = (iu + 1) < NU;
    bool de = (jv + 1) < NV;
    bool rd = re && de;

    F3 p0 = load3(pts + 3LL * k);
    F3 p1 = re ? load3(pts + 3LL * (k + 1))      : p0;  // right
    F3 p2 = de ? load3(pts + 3LL * (k + NU))     : p0;  // down
    F3 p3 = rd ? load3(pts + 3LL * (k + NU + 1)) : p0;  // diag

    out[OFF_LEN + 0LL * N + k] = re ? dist3(p0, p1) : 0.0f;
    out[OFF_LEN + 1LL * N + k] = rd ? dist3(p0, p3) : 0.0f;
    out[OFF_LEN + 2LL * N + k] = de ? dist3(p0, p2) : 0.0f;
    out[OFF_LEN + 3LL * N + k] = rd ? dist3(p1, p2) : 0.0f;

    float a0 = 0.0f, a1 = 0.0f;
    if (rd) {
        // tri 1: (k, k+1, k+nu+1)  -> cross(p1-p0, p3-p0)
        float e1x = p1.x - p0.x, e1y = p1.y - p0.y, e1z = p1.z - p0.z;
        float e2x = p3.x - p0.x, e2y = p3.y - p0.y, e2z = p3.z - p0.z;
        float cx = e1y * e2z - e1z * e2y;
        float cy = e1z * e2x - e1x * e2z;
        float cz = e1x * e2y - e1y * e2x;
        a0 = 0.5f * sqrtf(cx * cx + cy * cy + cz * cz + 1e-13f);
        // tri 2: (k, k+nu+1, k+nu) -> cross(p3-p0, p2-p0)
        float f2x = p2.x - p0.x, f2y = p2.y - p0.y, f2z = p2.z - p0.z;
        float dxx = e2y * f2z - e2z * f2y;
        float dyy = e2z * f2x - e2x * f2z;
        float dzz = e2x * f2y - e2y * f2x;
        a1 = 0.5f * sqrtf(dxx * dxx + dyy * dyy + dzz * dzz + 1e-13f);
    }
    out[OFF_AREA + 0LL * N + k] = a0;
    out[OFF_AREA + 1LL * N + k] = a1;
}

// ---------------------------------------------------------------------------
// Kernel 3: radii = mean of incident edge lengths (8-edge gather stencil).
// Matches scatter-mean of reference exactly (masked edges contribute 0/0).
// ---------------------------------------------------------------------------
__global__ __launch_bounds__(256)
void k_radii(const float* __restrict__ lens, float* __restrict__ rad) {
    int k = blockIdx.x * blockDim.x + threadIdx.x;
    if (k >= N) return;
    int iu = k & (NU - 1);
    int jv = k >> 10;
    bool re = (iu + 1) < NU;
    bool de = (jv + 1) < NV;
    bool le = iu > 0;        // has left column
    bool ue = jv > 0;        // has upper row

    float s = 0.0f; int c = 0;
    if (re)        { s += lens[0LL * N + k];          c++; }  // right (src)
    if (re && de)  { s += lens[1LL * N + k];          c++; }  // diag (src)
    if (de)        { s += lens[2LL * N + k];          c++; }  // down (src)
    if (le && de)  { s += lens[3LL * N + k - 1];      c++; }  // anti-diag (src = node+1)
    if (le)        { s += lens[0LL * N + k - 1];      c++; }  // right (dst)
    if (le && ue)  { s += lens[1LL * N + k - NU - 1]; c++; }  // diag (dst)
    if (ue)        { s += lens[2LL * N + k - NU];     c++; }  // down (dst)
    if (re && ue)  { s += lens[3LL * N + k - NU];     c++; }  // anti-diag (dst = node+nu)
    rad[k] = s / (float)max(c, 1);
}

// ---------------------------------------------------------------------------
// Launch
// ---------------------------------------------------------------------------
extern "C" void kernel_launch(void* const* d_in, const int* in_sizes, int n_in,
                              void* d_out, int out_size) {
    (void)in_sizes; (void)n_in; (void)out_size;
    // inputs: [0]=valid(bool, unused), [1]=candidates f32, [2]=candidates_norms f32, [3]=step(unused)
    const float* cand = (const float*)d_in[1];
    const float* cnrm = (const float*)d_in[2];
    float* out = (float*)d_out;

    const int T = 256;
    const int B = (N + T - 1) / T;

    k_gather<<<B, T>>>(cand, cnrm, out);
    k_edges<<<B, T>>>(out + OFF_PTS, out);
    k_radii<<<B, T>>>(out + OFF_LEN, out + OFF_RAD);
}

// round 2
// speedup vs baseline: 1.1633x; 1.1633x over previous
#include <cuda_runtime.h>
#include <cstdint>

// Fixed problem geometry: H=W=2048, step=2 -> nu=nv=1024, N=2^20 nodes.
constexpr int NU = 1024;
constexpr int NV = 1024;
constexpr int N  = NU * NV;        // 1048576
constexpr int W  = 2048;

// Output layout (concatenated tuple): pts[3N] nrm[3N] radii[N] lens[4N] areas[2N]
constexpr long long OFF_PTS  = 0;
constexpr long long OFF_NRM  = 3LL * N;
constexpr long long OFF_RAD  = 6LL * N;
constexpr long long OFF_LEN  = 7LL * N;
constexpr long long OFF_AREA = 11LL * N;

constexpr int BT = 256;  // block threads; 1024 % 256 == 0 -> block stays in one row

__device__ __forceinline__ float dist3c(float ax, float ay, float az,
                                        float bx, float by, float bz) {
    float dx = ax - bx, dy = ay - by, dz = az - bz;
    return sqrtf(dx * dx + dy * dy + dz * dz);
}

// ---------------------------------------------------------------------------
// Fused kernel: gather (pts/nrm) + edge lengths + triangle areas.
// Block covers 256 consecutive iu within one grid row jv. Anchor points of the
// own row and the down row are staged in smem (257 entries each) so neighbor
// point access is LDS, not repeated LDG.
// ---------------------------------------------------------------------------
__global__ __launch_bounds__(BT)
void k_fused(const float* __restrict__ cand,
             const float* __restrict__ cnrm,
             float* __restrict__ out) {
    __shared__ float sA[3 * (BT + 1)];   // own row anchors
    __shared__ float sB[3 * (BT + 1)];   // down row anchors

    int t = threadIdx.x;
    int k = blockIdx.x * BT + t;
    int iu = k & (NU - 1);
    int jv = k >> 10;
    bool re = (iu + 1) < NU;
    bool de = (jv + 1) < NV;
    bool rd = re && de;

    long long baseA = ((long long)(2 * jv) * W + 2 * iu) * 3;   // 8B-aligned
    long long baseB = de ? (baseA + 6LL * W) : baseA;           // clamp (guarded later)

    // own-row anchor
    float2 a01 = *reinterpret_cast<const float2*>(cand + baseA);
    float  a2  = cand[baseA + 2];
    sA[3 * t + 0] = a01.x; sA[3 * t + 1] = a01.y; sA[3 * t + 2] = a2;

    // down-row anchor
    float2 b01 = *reinterpret_cast<const float2*>(cand + baseB);
    float  b2  = cand[baseB + 2];
    sB[3 * t + 0] = b01.x; sB[3 * t + 1] = b01.y; sB[3 * t + 2] = b2;

    // normal (own only) — straight to registers
    float2 n01 = *reinterpret_cast<const float2*>(cnrm + baseA);
    float  n2  = cnrm[baseA + 2];

    // one thread loads the +1 extra column for this block
    if (t == 0) {
        int iuX = iu + BT;                     // t==0 -> iu is block base
        bool ex = iuX < NU;
        long long xA = ex ? (baseA + 6LL * BT) : baseA;       // clamp
        long long xB = (ex && de) ? (xA + 6LL * W) : xA;
        float2 xa01 = *reinterpret_cast<const float2*>(cand + xA);
        float  xa2  = cand[xA + 2];
        sA[3 * BT + 0] = xa01.x; sA[3 * BT + 1] = xa01.y; sA[3 * BT + 2] = xa2;
        float2 xb01 = *reinterpret_cast<const float2*>(cand + xB);
        float  xb2  = cand[xB + 2];
        sB[3 * BT + 0] = xb01.x; sB[3 * BT + 1] = xb01.y; sB[3 * BT + 2] = xb2;
    }
    __syncthreads();

    // p0 = own, p1 = right, p2 = down, p3 = diag
    float p0x = a01.x, p0y = a01.y, p0z = a2;
    float p1x = sA[3 * (t + 1) + 0], p1y = sA[3 * (t + 1) + 1], p1z = sA[3 * (t + 1) + 2];
    float p2x = sB[3 * t + 0],       p2y = sB[3 * t + 1],       p2z = sB[3 * t + 2];
    float p3x = sB[3 * (t + 1) + 0], p3y = sB[3 * (t + 1) + 1], p3z = sB[3 * (t + 1) + 2];

    // pts / nrm outputs
    float* po = out + OFF_PTS + 3LL * k;
    po[0] = p0x; po[1] = p0y; po[2] = p0z;
    float* no = out + OFF_NRM + 3LL * k;
    no[0] = n01.x; no[1] = n01.y; no[2] = n2;

    // edge lengths [right, diag, down, anti-diag]
    out[OFF_LEN + 0LL * N + k] = re ? dist3c(p0x, p0y, p0z, p1x, p1y, p1z) : 0.0f;
    out[OFF_LEN + 1LL * N + k] = rd ? dist3c(p0x, p0y, p0z, p3x, p3y, p3z) : 0.0f;
    out[OFF_LEN + 2LL * N + k] = de ? dist3c(p0x, p0y, p0z, p2x, p2y, p2z) : 0.0f;
    out[OFF_LEN + 3LL * N + k] = rd ? dist3c(p1x, p1y, p1z, p2x, p2y, p2z) : 0.0f;

    // triangle areas
    float e1x = p1x - p0x, e1y = p1y - p0y, e1z = p1z - p0z;   // to right
    float e2x = p3x - p0x, e2y = p3y - p0y, e2z = p3z - p0z;   // to diag
    float f2x = p2x - p0x, f2y = p2y - p0y, f2z = p2z - p0z;   // to down
    float cx = e1y * e2z - e1z * e2y;
    float cy = e1z * e2x - e1x * e2z;
    float cz = e1x * e2y - e1y * e2x;
    float dxx = e2y * f2z - e2z * f2y;
    float dyy = e2z * f2x - e2x * f2z;
    float dzz = e2x * f2y - e2y * f2x;
    float a0 = 0.5f * sqrtf(cx * cx + cy * cy + cz * cz + 1e-13f);
    float a1 = 0.5f * sqrtf(dxx * dxx + dyy * dyy + dzz * dzz + 1e-13f);
    out[OFF_AREA + 0LL * N + k] = rd ? a0 : 0.0f;
    out[OFF_AREA + 1LL * N + k] = rd ? a1 : 0.0f;
}

// ---------------------------------------------------------------------------
// radii = mean of incident edge lengths (8-edge gather stencil over lens).
// ---------------------------------------------------------------------------
__global__ __launch_bounds__(256)
void k_radii(const float* __restrict__ lens, float* __restrict__ rad) {
    int k = blockIdx.x * blockDim.x + threadIdx.x;
    if (k >= N) return;
    int iu = k & (NU - 1);
    int jv = k >> 10;
    bool re = (iu + 1) < NU;
    bool de = (jv + 1) < NV;
    bool le = iu > 0;
    bool ue = jv > 0;

    float s = 0.0f; int c = 0;
    if (re)        { s += lens[0LL * N + k];          c++; }  // right (src)
    if (re && de)  { s += lens[1LL * N + k];          c++; }  // diag (src)
    if (de)        { s += lens[2LL * N + k];          c++; }  // down (src)
    if (le && de)  { s += lens[3LL * N + k - 1];      c++; }  // anti-diag (src = node+1)
    if (le)        { s += lens[0LL * N + k - 1];      c++; }  // right (dst)
    if (le && ue)  { s += lens[1LL * N + k - NU - 1]; c++; }  // diag (dst)
    if (ue)        { s += lens[2LL * N + k - NU];     c++; }  // down (dst)
    if (re && ue)  { s += lens[3LL * N + k - NU];     c++; }  // anti-diag (dst = node+nu)
    rad[k] = s / (float)max(c, 1);
}

// ---------------------------------------------------------------------------
// Launch
// ---------------------------------------------------------------------------
extern "C" void kernel_launch(void* const* d_in, const int* in_sizes, int n_in,
                              void* d_out, int out_size) {
    (void)in_sizes; (void)n_in; (void)out_size;
    const float* cand = (const float*)d_in[1];
    const float* cnrm = (const float*)d_in[2];
    float* out = (float*)d_out;

    const int B = N / BT;
    k_fused<<<B, BT>>>(cand, cnrm, out);
    k_radii<<<B, BT>>>(out + OFF_LEN, out + OFF_RAD);
}

// round 3
// speedup vs baseline: 1.1844x; 1.0182x over previous
#include <cuda_runtime.h>
#include <cstdint>

// Fixed problem geometry: H=W=2048, step=2 -> nu=nv=1024, N=2^20 nodes.
constexpr int NU = 1024;
constexpr int NV = 1024;
constexpr int N  = NU * NV;        // 1048576
constexpr int W  = 2048;

// Output layout: pts[3N] nrm[3N] radii[N] lens[4N] areas[2N]
constexpr long long OFF_PTS  = 0;
constexpr long long OFF_NRM  = 3LL * N;
constexpr long long OFF_RAD  = 6LL * N;
constexpr long long OFF_LEN  = 7LL * N;
constexpr long long OFF_AREA = 11LL * N;

constexpr int BT = 256;  // threads/block; 1024 % 256 == 0 -> block within one grid row

__device__ __forceinline__ float dist3c(float ax, float ay, float az,
                                        float bx, float by, float bz) {
    float dx = ax - bx, dy = ay - by, dz = az - bz;
    return sqrtf(dx * dx + dy * dy + dz * dz);
}

// ---------------------------------------------------------------------------
// Single fused kernel: gather pts/nrm, edge lengths, triangle areas, radii.
// Block covers BT consecutive iu within one grid row jv. Anchor points of
// rows jv-1, jv, jv+1 (cols iu0-1 .. iu0+BT) staged in smem.
// ---------------------------------------------------------------------------
__global__ __launch_bounds__(BT)
void k_all(const float* __restrict__ cand,
           const float* __restrict__ cnrm,
           float* __restrict__ out) {
    // 3 rows x (BT+2) cols x 3 comps
    __shared__ float s[3][(BT + 2) * 3];

    int t  = threadIdx.x;
    int k  = blockIdx.x * BT + t;
    int iu = k & (NU - 1);
    int jv = k >> 10;
    int iu0 = blockIdx.x * BT & (NU - 1);     // block's first column

    bool re = (iu + 1) < NU;
    bool de = (jv + 1) < NV;
    bool le = iu > 0;
    bool ue = jv > 0;
    bool rd = re && de;

    // Clamped source rows (values behind a false flag are never used)
    int jvm = ue ? (jv - 1) : jv;
    int jvp = de ? (jv + 1) : jv;

    // anchor pixel addr: pix(iu,jv) = (2jv)*W + 2iu, elem addr = pix*3 (8B aligned)
    long long rowU = (long long)(2 * jvm) * W * 3;
    long long rowC = (long long)(2 * jv ) * W * 3;
    long long rowD = (long long)(2 * jvp) * W * 3;
    long long colB = 6LL * iu;

    // each thread loads col (t+1) of all 3 rows
    {
        float2 u01 = *reinterpret_cast<const float2*>(cand + rowU + colB);
        float  u2  = cand[rowU + colB + 2];
        s[0][3 * (t + 1) + 0] = u01.x; s[0][3 * (t + 1) + 1] = u01.y; s[0][3 * (t + 1) + 2] = u2;
        float2 c01 = *reinterpret_cast<const float2*>(cand + rowC + colB);
        float  c2  = cand[rowC + colB + 2];
        s[1][3 * (t + 1) + 0] = c01.x; s[1][3 * (t + 1) + 1] = c01.y; s[1][3 * (t + 1) + 2] = c2;
        float2 d01 = *reinterpret_cast<const float2*>(cand + rowD + colB);
        float  d2  = cand[rowD + colB + 2];
        s[2][3 * (t + 1) + 0] = d01.x; s[2][3 * (t + 1) + 1] = d01.y; s[2][3 * (t + 1) + 2] = d2;
    }

    // halo columns: t==0 -> left halo (iu0-1), t==1 -> right halo (iu0+BT)
    if (t < 2) {
        int iuH = (t == 0) ? (iu0 - 1) : (iu0 + BT);
        iuH = min(max(iuH, 0), NU - 1);                  // clamp (flag-guarded)
        int cH = (t == 0) ? 0 : (BT + 1);
        long long colH = 6LL * iuH;
        #pragma unroll
        for (int r = 0; r < 3; r++) {
            long long rowR = (r == 0) ? rowU : (r == 1) ? rowC : rowD;
            // rowU/rowC/rowD of thread t<2 are this block's rows (same jv for whole block)
            float2 h01 = *reinterpret_cast<const float2*>(cand + rowR + colH);
            float  h2  = cand[rowR + colH + 2];
            s[r][3 * cH + 0] = h01.x; s[r][3 * cH + 1] = h01.y; s[r][3 * cH + 2] = h2;
        }
    }

    // normal (own pixel) straight to registers
    float2 n01 = *reinterpret_cast<const float2*>(cnrm + rowC + colB);
    float  n2  = cnrm[rowC + colB + 2];

    __syncthreads();

    int c = t + 1;
    // 3x3 window
    float p0x = s[1][3 * c + 0],  p0y = s[1][3 * c + 1],  p0z = s[1][3 * c + 2];
    float qrx = s[1][3 * (c+1)],  qry = s[1][3 * (c+1)+1], qrz = s[1][3 * (c+1)+2];
    float qlx = s[1][3 * (c-1)],  qly = s[1][3 * (c-1)+1], qlz = s[1][3 * (c-1)+2];
    float qux = s[0][3 * c + 0],  quy = s[0][3 * c + 1],   quz = s[0][3 * c + 2];
    float qulx= s[0][3 * (c-1)],  quly= s[0][3 * (c-1)+1], qulz= s[0][3 * (c-1)+2];
    float qurx= s[0][3 * (c+1)],  qury= s[0][3 * (c+1)+1], qurz= s[0][3 * (c+1)+2];
    float qdx = s[2][3 * c + 0],  qdy = s[2][3 * c + 1],   qdz = s[2][3 * c + 2];
    float qdlx= s[2][3 * (c-1)],  qdly= s[2][3 * (c-1)+1], qdlz= s[2][3 * (c-1)+2];
    float qdrx= s[2][3 * (c+1)],  qdry= s[2][3 * (c+1)+1], qdrz= s[2][3 * (c+1)+2];

    // ---- outputs: pts / nrm ----
    float* po = out + OFF_PTS + 3LL * k;
    po[0] = p0x; po[1] = p0y; po[2] = p0z;
    float* no = out + OFF_NRM + 3LL * k;
    no[0] = n01.x; no[1] = n01.y; no[2] = n2;

    // ---- distances ----
    float dR  = dist3c(p0x, p0y, p0z, qrx,  qry,  qrz );  // right
    float dD  = dist3c(p0x, p0y, p0z, qdx,  qdy,  qdz );  // down
    float dG  = dist3c(p0x, p0y, p0z, qdrx, qdry, qdrz);  // diag
    float dAo = dist3c(qrx, qry, qrz, qdx,  qdy,  qdz );  // anti (lens output @ k)
    float dAL = dist3c(p0x, p0y, p0z, qdlx, qdly, qdlz);  // anti incident (edge @ k-1)
    float dL  = dist3c(p0x, p0y, p0z, qlx,  qly,  qlz );  // right(k-1)
    float dUL = dist3c(p0x, p0y, p0z, qulx, quly, qulz);  // diag(k-NU-1)
    float dU  = dist3c(p0x, p0y, p0z, qux,  quy,  quz );  // down(k-NU)
    float dUR = dist3c(p0x, p0y, p0z, qurx, qury, qurz);  // anti(k-NU)

    // ---- lens [right, diag, down, anti] ----
    out[OFF_LEN + 0LL * N + k] = re ? dR  : 0.0f;
    out[OFF_LEN + 1LL * N + k] = rd ? dG  : 0.0f;
    out[OFF_LEN + 2LL * N + k] = de ? dD  : 0.0f;
    out[OFF_LEN + 3LL * N + k] = rd ? dAo : 0.0f;

    // ---- radii: mean over existing incident edges ----
    float sum = 0.0f; int cnt = 0;
    if (re)       { sum += dR;  cnt++; }
    if (rd)       { sum += dG;  cnt++; }
    if (de)       { sum += dD;  cnt++; }
    if (le && de) { sum += dAL; cnt++; }
    if (le)       { sum += dL;  cnt++; }
    if (le && ue) { sum += dUL; cnt++; }
    if (ue)       { sum += dU;  cnt++; }
    if (re && ue) { sum += dUR; cnt++; }
    out[OFF_RAD + k] = sum / (float)max(cnt, 1);

    // ---- areas ----
    float e1x = qrx - p0x, e1y = qry - p0y, e1z = qrz - p0z;
    float e2x = qdrx - p0x, e2y = qdry - p0y, e2z = qdrz - p0z;
    float f2x = qdx - p0x, f2y = qdy - p0y, f2z = qdz - p0z;
    float cx = e1y * e2z - e1z * e2y;
    float cy = e1z * e2x - e1x * e2z;
    float cz = e1x * e2y - e1y * e2x;
    float gx = e2y * f2z - e2z * f2y;
    float gy = e2z * f2x - e2x * f2z;
    float gz = e2x * f2y - e2y * f2x;
    float a0 = 0.5f * sqrtf(cx * cx + cy * cy + cz * cz + 1e-13f);
    float a1 = 0.5f * sqrtf(gx * gx + gy * gy + gz * gz + 1e-13f);
    out[OFF_AREA + 0LL * N + k] = rd ? a0 : 0.0f;
    out[OFF_AREA + 1LL * N + k] = rd ? a1 : 0.0f;
}

// ---------------------------------------------------------------------------
// Launch
// ---------------------------------------------------------------------------
extern "C" void kernel_launch(void* const* d_in, const int* in_sizes, int n_in,
                              void* d_out, int out_size) {
    (void)in_sizes; (void)n_in; (void)out_size;
    const float* cand = (const float*)d_in[1];
    const float* cnrm = (const float*)d_in[2];
    float* out = (float*)d_out;

    k_all<<<N / BT, BT>>>(cand, cnrm, out);
}

// round 4
// speedup vs baseline: 1.3756x; 1.1614x over previous
#include <cuda_runtime.h>
#include <cstdint>

// Fixed problem geometry: H=W=2048, step=2 -> nu=nv=1024, N=2^20 nodes.
constexpr int NU = 1024;
constexpr int NV = 1024;
constexpr int N  = NU * NV;        // 1048576
constexpr int W  = 2048;

// Output layout: pts[3N] nrm[3N] radii[N] lens[4N] areas[2N]
constexpr long long OFF_PTS  = 0;
constexpr long long OFF_NRM  = 3LL * N;
constexpr long long OFF_RAD  = 6LL * N;
constexpr long long OFF_LEN  = 7LL * N;
constexpr long long OFF_AREA = 11LL * N;

constexpr int BT = 256;  // threads/block; 1024 % 256 == 0 -> block within one grid row

// Fast sqrt: single MUFU.RSQ + FMUL. x >= 0. Guard makes x==0 -> 0 (not NaN).
__device__ __forceinline__ float fast_sqrt(float x) {
    return x * rsqrtf(fmaxf(x, 1e-30f));
}

__device__ __forceinline__ float dist3c(float ax, float ay, float az,
                                        float bx, float by, float bz) {
    float dx = ax - bx, dy = ay - by, dz = az - bz;
    return fast_sqrt(dx * dx + dy * dy + dz * dz);
}

// ---------------------------------------------------------------------------
// Single fused kernel: gather pts/nrm, edge lengths, triangle areas, radii.
// Block covers BT consecutive iu within one grid row jv. Anchor points of
// rows jv-1, jv, jv+1 (cols iu0-1 .. iu0+BT) staged in smem.
// ---------------------------------------------------------------------------
__global__ __launch_bounds__(BT)
void k_all(const float* __restrict__ cand,
           const float* __restrict__ cnrm,
           float* __restrict__ out) {
    __shared__ float s[3][(BT + 2) * 3];   // 3 rows x (BT+2) cols x xyz

    int t  = threadIdx.x;
    int k  = blockIdx.x * BT + t;
    int iu = k & (NU - 1);
    int jv = k >> 10;
    int iu0 = blockIdx.x * BT & (NU - 1);

    bool re = (iu + 1) < NU;
    bool de = (jv + 1) < NV;
    bool le = iu > 0;
    bool ue = jv > 0;
    bool rd = re && de;

    int jvm = ue ? (jv - 1) : jv;
    int jvp = de ? (jv + 1) : jv;

    long long rowU = (long long)(2 * jvm) * W * 3;
    long long rowC = (long long)(2 * jv ) * W * 3;
    long long rowD = (long long)(2 * jvp) * W * 3;
    long long colB = 6LL * iu;

    // each thread loads col (t+1) of all 3 rows
    {
        float2 u01 = *reinterpret_cast<const float2*>(cand + rowU + colB);
        float  u2  = cand[rowU + colB + 2];
        s[0][3 * (t + 1) + 0] = u01.x; s[0][3 * (t + 1) + 1] = u01.y; s[0][3 * (t + 1) + 2] = u2;
        float2 c01 = *reinterpret_cast<const float2*>(cand + rowC + colB);
        float  c2  = cand[rowC + colB + 2];
        s[1][3 * (t + 1) + 0] = c01.x; s[1][3 * (t + 1) + 1] = c01.y; s[1][3 * (t + 1) + 2] = c2;
        float2 d01 = *reinterpret_cast<const float2*>(cand + rowD + colB);
        float  d2  = cand[rowD + colB + 2];
        s[2][3 * (t + 1) + 0] = d01.x; s[2][3 * (t + 1) + 1] = d01.y; s[2][3 * (t + 1) + 2] = d2;
    }

    // halo columns: t==0 -> left halo (iu0-1), t==1 -> right halo (iu0+BT)
    if (t < 2) {
        int iuH = (t == 0) ? (iu0 - 1) : (iu0 + BT);
        iuH = min(max(iuH, 0), NU - 1);                  // clamp (flag-guarded)
        int cH = (t == 0) ? 0 : (BT + 1);
        long long colH = 6LL * iuH;
        #pragma unroll
        for (int r = 0; r < 3; r++) {
            long long rowR = (r == 0) ? rowU : (r == 1) ? rowC : rowD;
            float2 h01 = *reinterpret_cast<const float2*>(cand + rowR + colH);
            float  h2  = cand[rowR + colH + 2];
            s[r][3 * cH + 0] = h01.x; s[r][3 * cH + 1] = h01.y; s[r][3 * cH + 2] = h2;
        }
    }

    // normal (own pixel) straight to registers
    float2 n01 = *reinterpret_cast<const float2*>(cnrm + rowC + colB);
    float  n2  = cnrm[rowC + colB + 2];

    __syncthreads();

    int c = t + 1;
    float p0x = s[1][3 * c + 0],  p0y = s[1][3 * c + 1],  p0z = s[1][3 * c + 2];
    float qrx = s[1][3 * (c+1)],  qry = s[1][3 * (c+1)+1], qrz = s[1][3 * (c+1)+2];
    float qlx = s[1][3 * (c-1)],  qly = s[1][3 * (c-1)+1], qlz = s[1][3 * (c-1)+2];
    float qux = s[0][3 * c + 0],  quy = s[0][3 * c + 1],   quz = s[0][3 * c + 2];
    float qulx= s[0][3 * (c-1)],  quly= s[0][3 * (c-1)+1], qulz= s[0][3 * (c-1)+2];
    float qurx= s[0][3 * (c+1)],  qury= s[0][3 * (c+1)+1], qurz= s[0][3 * (c+1)+2];
    float qdx = s[2][3 * c + 0],  qdy = s[2][3 * c + 1],   qdz = s[2][3 * c + 2];
    float qdlx= s[2][3 * (c-1)],  qdly= s[2][3 * (c-1)+1], qdlz= s[2][3 * (c-1)+2];
    float qdrx= s[2][3 * (c+1)],  qdry= s[2][3 * (c+1)+1], qdrz= s[2][3 * (c+1)+2];

    // ---- pts / nrm ----
    float* po = out + OFF_PTS + 3LL * k;
    po[0] = p0x; po[1] = p0y; po[2] = p0z;
    float* no = out + OFF_NRM + 3LL * k;
    no[0] = n01.x; no[1] = n01.y; no[2] = n2;

    // ---- distances (8-neighborhood + anti edge at k) ----
    float dR  = dist3c(p0x, p0y, p0z, qrx,  qry,  qrz );
    float dD  = dist3c(p0x, p0y, p0z, qdx,  qdy,  qdz );
    float dG  = dist3c(p0x, p0y, p0z, qdrx, qdry, qdrz);
    float dAo = dist3c(qrx, qry, qrz, qdx,  qdy,  qdz );
    float dAL = dist3c(p0x, p0y, p0z, qdlx, qdly, qdlz);
    float dL  = dist3c(p0x, p0y, p0z, qlx,  qly,  qlz );
    float dUL = dist3c(p0x, p0y, p0z, qulx, quly, qulz);
    float dU  = dist3c(p0x, p0y, p0z, qux,  quy,  quz );
    float dUR = dist3c(p0x, p0y, p0z, qurx, qury, qurz);

    // ---- lens [right, diag, down, anti] ----
    out[OFF_LEN + 0LL * N + k] = re ? dR  : 0.0f;
    out[OFF_LEN + 1LL * N + k] = rd ? dG  : 0.0f;
    out[OFF_LEN + 2LL * N + k] = de ? dD  : 0.0f;
    out[OFF_LEN + 3LL * N + k] = rd ? dAo : 0.0f;

    // ---- radii: mean over existing incident edges ----
    float sum = 0.0f; int cnt = 0;
    if (re)       { sum += dR;  cnt++; }
    if (rd)       { sum += dG;  cnt++; }
    if (de)       { sum += dD;  cnt++; }
    if (le && de) { sum += dAL; cnt++; }
    if (le)       { sum += dL;  cnt++; }
    if (le && ue) { sum += dUL; cnt++; }
    if (ue)       { sum += dU;  cnt++; }
    if (re && ue) { sum += dUR; cnt++; }
    out[OFF_RAD + k] = sum / (float)max(cnt, 1);

    // ---- areas ----
    float e1x = qrx - p0x,  e1y = qry - p0y,  e1z = qrz - p0z;
    float e2x = qdrx - p0x, e2y = qdry - p0y, e2z = qdrz - p0z;
    float f2x = qdx - p0x,  f2y = qdy - p0y,  f2z = qdz - p0z;
    float cx = e1y * e2z - e1z * e2y;
    float cy = e1z * e2x - e1x * e2z;
    float cz = e1x * e2y - e1y * e2x;
    float gx = e2y * f2z - e2z * f2y;
    float gy = e2z * f2x - e2x * f2z;
    float gz = e2x * f2y - e2y * f2x;
    float a0 = 0.5f * fast_sqrt(cx * cx + cy * cy + cz * cz + 1e-13f);
    float a1 = 0.5f * fast_sqrt(gx * gx + gy * gy + gz * gz + 1e-13f);
    out[OFF_AREA + 0LL * N + k] = rd ? a0 : 0.0f;
    out[OFF_AREA + 1LL * N + k] = rd ? a1 : 0.0f;
}

// ---------------------------------------------------------------------------
// Launch
// ---------------------------------------------------------------------------
extern "C" void kernel_launch(void* const* d_in, const int* in_sizes, int n_in,
                              void* d_out, int out_size) {
    (void)in_sizes; (void)n_in; (void)out_size;
    const float* cand = (const float*)d_in[1];
    const float* cnrm = (const float*)d_in[2];
    float* out = (float*)d_out;

    k_all<<<N / BT, BT>>>(cand, cnrm, out);
}